// round 16
// baseline (speedup 1.0000x reference)
#include <cstdint>
#include <cuda_runtime.h>
#include <cuda_bf16.h>
#include <math_constants.h>

#define Bn 16
#define Sn 2048
#define Dn 768
#define D4 192                       // Dn/4
#define NORM_CONST 0.0360843918243516127f  // 1/sqrt(768)

// attn geometry
#define CHUNK_ROWS 128
#define CHUNKS_PER_B 16
#define NCHUNK 256
#define ATT_STAGES 4
#define RPS 8
#define STAGE_F4 (RPS * D4)          // 1536 float4
#define STAGE_BYTES (STAGE_F4 * 16)  // 24576
#define NSTAGE_ITERS (CHUNK_ROWS / RPS)  // 16

#define NBLK 256                     // tail grid; occ 2/SM -> all resident

// ---------------- scratch ----------------
__device__ float g_qk[Bn * Dn];
__device__ float g_pm[NCHUNK];
__device__ float g_pl[NCHUNK];
__device__ float g_pacc[(size_t)NCHUNK * Dn];
__device__ float g_c[Bn * Dn];
__device__ unsigned g_bar_count;
__device__ unsigned g_bar_gen;

// ---------------- helpers ----------------
__device__ __forceinline__ float warp_sum(float v) {
    #pragma unroll
    for (int off = 16; off > 0; off >>= 1)
        v += __shfl_xor_sync(0xffffffffu, v, off);
    return v;
}

__device__ __forceinline__ void cp_async16(unsigned int dst, const void* src) {
    asm volatile("cp.async.cg.shared.global [%0], [%1], 16;" :: "r"(dst), "l"(src));
}
__device__ __forceinline__ void cp_commit() {
    asm volatile("cp.async.commit_group;");
}
__device__ __forceinline__ void cp_wait_all() {
    asm volatile("cp.async.wait_group 0;");
}

// packed f32x2 ops (sm_103a)
__device__ __forceinline__ unsigned long long fma2(unsigned long long a,
                                                   unsigned long long b,
                                                   unsigned long long c) {
    unsigned long long d;
    asm("fma.rn.f32x2 %0, %1, %2, %3;" : "=l"(d) : "l"(a), "l"(b), "l"(c));
    return d;
}
__device__ __forceinline__ unsigned long long mul2(unsigned long long a,
                                                   unsigned long long b) {
    unsigned long long d;
    asm("mul.rn.f32x2 %0, %1, %2;" : "=l"(d) : "l"(a), "l"(b));
    return d;
}
__device__ __forceinline__ unsigned long long pack2(float a, float b) {
    unsigned long long r;
    asm("mov.b64 %0, {%1, %2};" : "=l"(r) : "f"(a), "f"(b));
    return r;
}
__device__ __forceinline__ void unpack2(unsigned long long v, float& a, float& b) {
    asm("mov.b64 {%0, %1}, %2;" : "=f"(a), "=f"(b) : "l"(v));
}

// sense-reversal grid barrier; all NBLK blocks co-resident (2/SM at 96KB smem).
__device__ __forceinline__ void grid_barrier() {
    __syncthreads();
    if (threadIdx.x == 0) {
        __threadfence();
        unsigned gen = *(volatile unsigned*)&g_bar_gen;
        unsigned arrived = atomicAdd(&g_bar_count, 1u);
        if (arrived == NBLK - 1) {
            g_bar_count = 0;
            __threadfence();
            atomicAdd(&g_bar_gen, 1u);
        } else {
            while (*(volatile unsigned*)&g_bar_gen == gen) __nanosleep(64);
        }
        __threadfence();
    }
    __syncthreads();
}

// ============ K1: fused q0 = Wq x0, qk += Wk^T q0 (unchanged, proven) ============
__global__ void __launch_bounds__(256) fused_q0qk(
    float* __restrict__ qk, const float* __restrict__ Wq,
    const float* __restrict__ Wk, const float* __restrict__ b_in)
{
    extern __shared__ float xs[];
    __shared__ float q0s[8 * Bn];
    int tid = threadIdx.x, warp = tid >> 5, lane = tid & 31;
    int e0 = blockIdx.x * 8;

    {
        unsigned int sb = (unsigned int)__cvta_generic_to_shared(xs);
        const float4* src4 = (const float4*)b_in;
        #pragma unroll
        for (int i = 0; i < 12; i++) {
            int idx = i * 256 + tid;
            int b = idx / D4, d4 = idx - b * D4;
            cp_async16(sb + idx * 16, src4 + (size_t)b * Sn * D4 + d4);
        }
        cp_commit();
    }

    int e = e0 + warp;
    const float4* wr = (const float4*)(Wq + (size_t)e * Dn);
    float4 wf[6];
    #pragma unroll
    for (int i = 0; i < 6; i++) wf[i] = wr[i * 32 + lane];

    cp_wait_all();
    __syncthreads();

    {
        const float4* xs4 = (const float4*)xs;
        float acc[Bn];
        #pragma unroll
        for (int b = 0; b < Bn; b++) acc[b] = 0.f;
        #pragma unroll
        for (int i = 0; i < 6; i++) {
            float4 w = wf[i];
            #pragma unroll
            for (int b = 0; b < Bn; b++) {
                float4 x = xs4[b * D4 + i * 32 + lane];
                acc[b] = fmaf(w.x, x.x, fmaf(w.y, x.y, fmaf(w.z, x.z, fmaf(w.w, x.w, acc[b]))));
            }
        }
        #pragma unroll
        for (int b = 0; b < Bn; b++) {
            float v = warp_sum(acc[b]);
            if (lane == 0) q0s[warp * Bn + b] = v;
        }
    }
    __syncthreads();

    {
        float a0[Bn], a1[Bn], a2[Bn];
        #pragma unroll
        for (int b = 0; b < Bn; b++) { a0[b] = a1[b] = a2[b] = 0.f; }
        #pragma unroll
        for (int ee = 0; ee < 8; ee++) {
            const float* wkr = Wk + (size_t)(e0 + ee) * Dn;
            float w0 = wkr[tid], w1 = wkr[tid + 256], w2 = wkr[tid + 512];
            #pragma unroll
            for (int b = 0; b < Bn; b++) {
                float q = q0s[ee * Bn + b];
                a0[b] = fmaf(q, w0, a0[b]);
                a1[b] = fmaf(q, w1, a1[b]);
                a2[b] = fmaf(q, w2, a2[b]);
            }
        }
        #pragma unroll
        for (int b = 0; b < Bn; b++) {
            atomicAdd(&qk[b * Dn + tid],       a0[b]);
            atomicAdd(&qk[b * Dn + tid + 256], a1[b]);
            atomicAdd(&qk[b * Dn + tid + 512], a2[b]);
        }
    }
}

// ============ K2: persistent tail = attn streaming + combine + Wv matvec ============
__global__ void __launch_bounds__(256, 2) fused_tail(
    const float* __restrict__ b_in, const float* __restrict__ Wv,
    float* __restrict__ out)
{
    extern __shared__ float smem[];            // 96 KB
    __shared__ float msm[8], lsm[8];
    int tid = threadIdx.x, warp = tid >> 5, lane = tid & 31;
    int blk = blockIdx.x;
    unsigned int sb = (unsigned int)__cvta_generic_to_shared(smem);
    float4* smem4 = (float4*)smem;

    // ---------- Phase A: streaming online-softmax (f32x2 + lazy rescale) ----------
    {
        int b = blk >> 4, c = blk & (CHUNKS_PER_B - 1);

        const ulonglong2* qkv2 = (const ulonglong2*)(g_qk + b * Dn);
        ulonglong2 q2[6];
        #pragma unroll
        for (int i = 0; i < 6; i++) q2[i] = qkv2[i * 32 + lane];

        const float4* xb4 = (const float4*)b_in + ((size_t)b * Sn + (size_t)c * CHUNK_ROWS) * D4;

        #pragma unroll
        for (int s = 0; s < ATT_STAGES - 1; s++) {
            const float4* src = xb4 + (size_t)s * STAGE_F4;
            unsigned int dst = sb + s * STAGE_BYTES;
            #pragma unroll
            for (int i = 0; i < 6; i++) {
                int idx = i * 256 + tid;
                cp_async16(dst + idx * 16, src + idx);
            }
            cp_commit();
        }

        float m = -CUDART_INF_F, l = 0.f;
        ulonglong2 acc[6];
        #pragma unroll
        for (int i = 0; i < 6; i++) { acc[i].x = 0ull; acc[i].y = 0ull; }

        for (int t = 0; t < NSTAGE_ITERS; t++) {
            if (t + ATT_STAGES - 1 < NSTAGE_ITERS) {
                int sn = t + ATT_STAGES - 1;
                const float4* src = xb4 + (size_t)sn * STAGE_F4;
                unsigned int dst = sb + (sn & (ATT_STAGES - 1)) * STAGE_BYTES;
                #pragma unroll
                for (int i = 0; i < 6; i++) {
                    int idx = i * 256 + tid;
                    cp_async16(dst + idx * 16, src + idx);
                }
            }
            cp_commit();
            asm volatile("cp.async.wait_group 3;");
            __syncthreads();

            const ulonglong2* row =
                (const ulonglong2*)(smem4 + (size_t)(t & (ATT_STAGES - 1)) * STAGE_F4 + warp * D4);
            ulonglong2 cu[6];
            #pragma unroll
            for (int i = 0; i < 6; i++) cu[i] = row[i * 32 + lane];

            // packed dot: 12 FFMA2 instead of 24 FFMA
            unsigned long long d0 = 0ull, d1 = 0ull;
            #pragma unroll
            for (int i = 0; i < 6; i++) {
                d0 = fma2(q2[i].x, cu[i].x, d0);
                d1 = fma2(q2[i].y, cu[i].y, d1);
            }
            float p0, p1, p2, p3;
            unpack2(d0, p0, p1);
            unpack2(d1, p2, p3);
            float score = warp_sum((p0 + p2) + (p1 + p3)) * NORM_CONST;

            if (score > m) {
                // rare path (~ln(128) times/chunk, warp-uniform): rescale
                float corr = __expf(m - score);   // m=-inf -> 0 on first row
                float w = 1.f;                    // exp(score - score)
                l = l * corr + w;
                unsigned long long w2 = pack2(w, w);
                unsigned long long c2 = pack2(corr, corr);
                #pragma unroll
                for (int i = 0; i < 6; i++) {
                    acc[i].x = fma2(w2, cu[i].x, mul2(c2, acc[i].x));
                    acc[i].y = fma2(w2, cu[i].y, mul2(c2, acc[i].y));
                }
                m = score;
            } else {
                // fast path: 12 FFMA2, no rescale
                float w = __expf(score - m);
                l += w;
                unsigned long long w2 = pack2(w, w);
                #pragma unroll
                for (int i = 0; i < 6; i++) {
                    acc[i].x = fma2(w2, cu[i].x, acc[i].x);
                    acc[i].y = fma2(w2, cu[i].y, acc[i].y);
                }
            }
            __syncthreads();
        }

        // merge 8 warp partials -> 1 chunk partial (bit-layout identical to float4)
        ulonglong2* accsm = (ulonglong2*)smem4;
        #pragma unroll
        for (int i = 0; i < 6; i++) accsm[warp * D4 + i * 32 + lane] = acc[i];
        if (lane == 0) { msm[warp] = m; lsm[warp] = l; }
        __syncthreads();

        if (tid < D4) {
            float M = -CUDART_INF_F;
            #pragma unroll
            for (int w = 0; w < 8; w++) M = fmaxf(M, msm[w]);
            float L = 0.f;
            float4 s = make_float4(0.f, 0.f, 0.f, 0.f);
            #pragma unroll
            for (int w = 0; w < 8; w++) {
                float ef = __expf(msm[w] - M);
                L = fmaf(ef, lsm[w], L);
                float4 a = smem4[w * D4 + tid];
                s.x = fmaf(ef, a.x, s.x);
                s.y = fmaf(ef, a.y, s.y);
                s.z = fmaf(ef, a.z, s.z);
                s.w = fmaf(ef, a.w, s.w);
            }
            ((float4*)g_pacc)[(size_t)blk * D4 + tid] = s;
            if (tid == 0) { g_pm[blk] = M; g_pl[blk] = L; }
        }
    }

    grid_barrier();

    // ---------- Phase B: split-softmax combine (blocks 0..15) ----------
    if (blk < Bn && tid < D4) {
        int b = blk, d4 = tid;
        const float* pm = g_pm + b * CHUNKS_PER_B;
        const float* pl = g_pl + b * CHUNKS_PER_B;
        float M = -CUDART_INF_F;
        #pragma unroll
        for (int j = 0; j < CHUNKS_PER_B; j++) M = fmaxf(M, pm[j]);
        float L = 0.f;
        float4 s = make_float4(0.f, 0.f, 0.f, 0.f);
        const float4* pacc4 = (const float4*)g_pacc;
        #pragma unroll
        for (int j = 0; j < CHUNKS_PER_B; j++) {
            float ef = __expf(pm[j] - M);
            L = fmaf(ef, pl[j], L);
            float4 a = pacc4[(size_t)(b * CHUNKS_PER_B + j) * D4 + d4];
            s.x = fmaf(ef, a.x, s.x);
            s.y = fmaf(ef, a.y, s.y);
            s.z = fmaf(ef, a.z, s.z);
            s.w = fmaf(ef, a.w, s.w);
        }
        float inv = 1.f / L;
        ((float4*)g_c)[b * D4 + d4] = make_float4(s.x * inv, s.y * inv, s.z * inv, s.w * inv);
    }

    grid_barrier();

    // ---------- Phase C: out[b][e] = Wv[e] . c[b], 3 e-rows per block ----------
    {
        const float4* src4 = (const float4*)g_c;
        #pragma unroll
        for (int i = 0; i < 12; i++) {
            int idx = i * 256 + tid;
            cp_async16(sb + idx * 16, src4 + idx);
        }
        cp_commit();

        int e = blk * 3 + warp;
        float4 wf[6];
        if (warp < 3) {
            const float4* wr = (const float4*)(Wv + (size_t)e * Dn);
            #pragma unroll
            for (int i = 0; i < 6; i++) wf[i] = wr[i * 32 + lane];
        }
        cp_wait_all();
        __syncthreads();

        if (warp < 3) {
            const float4* xs4 = (const float4*)smem;
            float acc[Bn];
            #pragma unroll
            for (int b = 0; b < Bn; b++) acc[b] = 0.f;
            #pragma unroll
            for (int i = 0; i < 6; i++) {
                float4 w = wf[i];
                #pragma unroll
                for (int b = 0; b < Bn; b++) {
                    float4 x = xs4[b * D4 + i * 32 + lane];
                    acc[b] = fmaf(w.x, x.x, fmaf(w.y, x.y, fmaf(w.z, x.z, fmaf(w.w, x.w, acc[b]))));
                }
            }
            #pragma unroll
            for (int b = 0; b < Bn; b++) {
                float v = warp_sum(acc[b]);
                if (lane == 0) out[b * Dn + e] = v;
            }
        }
    }
}

// ---------------- launch ----------------
extern "C" void kernel_launch(void* const* d_in, const int* in_sizes, int n_in,
                              void* d_out, int out_size)
{
    const float* b_in = (const float*)d_in[0];
    // d_in[1] = mask (int64): masks whole QUERY rows only; query row 0 is always
    // unmasked and the output only uses query row 0 -> mask is irrelevant.
    const float* Wq = (const float*)d_in[2];
    const float* Wk = (const float*)d_in[3];
    const float* Wv = (const float*)d_in[4];
    float* out = (float*)d_out;

    float* qk; cudaGetSymbolAddress((void**)&qk, g_qk);

    cudaFuncSetAttribute(fused_q0qk, cudaFuncAttributeMaxDynamicSharedMemorySize, 49152);
    cudaFuncSetAttribute(fused_tail, cudaFuncAttributeMaxDynamicSharedMemorySize,
                         ATT_STAGES * STAGE_BYTES);

    cudaMemsetAsync(qk, 0, Bn * Dn * sizeof(float), 0);
    fused_q0qk<<<96, 256, 49152>>>(qk, Wq, Wk, b_in);
    fused_tail<<<NBLK, 256, ATT_STAGES * STAGE_BYTES>>>(b_in, Wv, out);
}

// round 17
// speedup vs baseline: 1.0091x; 1.0091x over previous
#include <cstdint>
#include <cuda_runtime.h>
#include <cuda_bf16.h>
#include <math_constants.h>

#define Bn 16
#define Sn 2048
#define Dn 768
#define D4 192                       // Dn/4
#define NORM_CONST 0.0360843918243516127f  // 1/sqrt(768)

// attn geometry: 2 stages x 16 rows, 2 rows per warp per iteration
#define CHUNK_ROWS 128
#define CHUNKS_PER_B 16
#define NCHUNK 256
#define ATT_STAGES 2
#define RPS 16
#define STAGE_F4 (RPS * D4)          // 3072 float4
#define STAGE_BYTES (STAGE_F4 * 16)  // 49152
#define NSTAGE_ITERS (CHUNK_ROWS / RPS)  // 8

#define NBLK 256                     // tail grid; occ 2/SM -> all resident

// ---------------- scratch ----------------
__device__ float g_qk[Bn * Dn];
__device__ float g_pm[NCHUNK];
__device__ float g_pl[NCHUNK];
__device__ float g_pacc[(size_t)NCHUNK * Dn];
__device__ float g_c[Bn * Dn];
__device__ unsigned g_bar_count;
__device__ unsigned g_bar_gen;

// ---------------- helpers ----------------
__device__ __forceinline__ float warp_sum(float v) {
    #pragma unroll
    for (int off = 16; off > 0; off >>= 1)
        v += __shfl_xor_sync(0xffffffffu, v, off);
    return v;
}
// two independent reductions, shfl latencies overlapped
__device__ __forceinline__ void warp_sum2(float& a, float& b) {
    #pragma unroll
    for (int off = 16; off > 0; off >>= 1) {
        a += __shfl_xor_sync(0xffffffffu, a, off);
        b += __shfl_xor_sync(0xffffffffu, b, off);
    }
}

__device__ __forceinline__ void cp_async16(unsigned int dst, const void* src) {
    asm volatile("cp.async.cg.shared.global [%0], [%1], 16;" :: "r"(dst), "l"(src));
}
__device__ __forceinline__ void cp_commit() {
    asm volatile("cp.async.commit_group;");
}
__device__ __forceinline__ void cp_wait_all() {
    asm volatile("cp.async.wait_group 0;");
}

// sense-reversal grid barrier; all NBLK blocks co-resident (2/SM at 96KB smem).
__device__ __forceinline__ void grid_barrier() {
    __syncthreads();
    if (threadIdx.x == 0) {
        __threadfence();
        unsigned gen = *(volatile unsigned*)&g_bar_gen;
        unsigned arrived = atomicAdd(&g_bar_count, 1u);
        if (arrived == NBLK - 1) {
            g_bar_count = 0;
            __threadfence();
            atomicAdd(&g_bar_gen, 1u);
        } else {
            while (*(volatile unsigned*)&g_bar_gen == gen) __nanosleep(64);
        }
        __threadfence();
    }
    __syncthreads();
}

// ============ K1: fused q0 = Wq x0, qk += Wk^T q0 (unchanged, proven) ============
__global__ void __launch_bounds__(256) fused_q0qk(
    float* __restrict__ qk, const float* __restrict__ Wq,
    const float* __restrict__ Wk, const float* __restrict__ b_in)
{
    extern __shared__ float xs[];
    __shared__ float q0s[8 * Bn];
    int tid = threadIdx.x, warp = tid >> 5, lane = tid & 31;
    int e0 = blockIdx.x * 8;

    {
        unsigned int sb = (unsigned int)__cvta_generic_to_shared(xs);
        const float4* src4 = (const float4*)b_in;
        #pragma unroll
        for (int i = 0; i < 12; i++) {
            int idx = i * 256 + tid;
            int b = idx / D4, d4 = idx - b * D4;
            cp_async16(sb + idx * 16, src4 + (size_t)b * Sn * D4 + d4);
        }
        cp_commit();
    }

    int e = e0 + warp;
    const float4* wr = (const float4*)(Wq + (size_t)e * Dn);
    float4 wf[6];
    #pragma unroll
    for (int i = 0; i < 6; i++) wf[i] = wr[i * 32 + lane];

    cp_wait_all();
    __syncthreads();

    {
        const float4* xs4 = (const float4*)xs;
        float acc[Bn];
        #pragma unroll
        for (int b = 0; b < Bn; b++) acc[b] = 0.f;
        #pragma unroll
        for (int i = 0; i < 6; i++) {
            float4 w = wf[i];
            #pragma unroll
            for (int b = 0; b < Bn; b++) {
                float4 x = xs4[b * D4 + i * 32 + lane];
                acc[b] = fmaf(w.x, x.x, fmaf(w.y, x.y, fmaf(w.z, x.z, fmaf(w.w, x.w, acc[b]))));
            }
        }
        #pragma unroll
        for (int b = 0; b < Bn; b++) {
            float v = warp_sum(acc[b]);
            if (lane == 0) q0s[warp * Bn + b] = v;
        }
    }
    __syncthreads();

    {
        float a0[Bn], a1[Bn], a2[Bn];
        #pragma unroll
        for (int b = 0; b < Bn; b++) { a0[b] = a1[b] = a2[b] = 0.f; }
        #pragma unroll
        for (int ee = 0; ee < 8; ee++) {
            const float* wkr = Wk + (size_t)(e0 + ee) * Dn;
            float w0 = wkr[tid], w1 = wkr[tid + 256], w2 = wkr[tid + 512];
            #pragma unroll
            for (int b = 0; b < Bn; b++) {
                float q = q0s[ee * Bn + b];
                a0[b] = fmaf(q, w0, a0[b]);
                a1[b] = fmaf(q, w1, a1[b]);
                a2[b] = fmaf(q, w2, a2[b]);
            }
        }
        #pragma unroll
        for (int b = 0; b < Bn; b++) {
            atomicAdd(&qk[b * Dn + tid],       a0[b]);
            atomicAdd(&qk[b * Dn + tid + 256], a1[b]);
            atomicAdd(&qk[b * Dn + tid + 512], a2[b]);
        }
    }
}

// ============ K2: persistent tail = attn streaming + combine + Wv matvec ============
__global__ void __launch_bounds__(256, 2) fused_tail(
    const float* __restrict__ b_in, const float* __restrict__ Wv,
    float* __restrict__ out)
{
    extern __shared__ float smem[];            // 96 KB: 2 stages x 16 rows
    __shared__ float msm[8], lsm[8];
    int tid = threadIdx.x, warp = tid >> 5, lane = tid & 31;
    int blk = blockIdx.x;
    unsigned int sb = (unsigned int)__cvta_generic_to_shared(smem);
    float4* smem4 = (float4*)smem;

    // ---------- Phase A: streaming online-softmax, 2 rows per warp per stage ----------
    {
        int b = blk >> 4, c = blk & (CHUNKS_PER_B - 1);

        const float4* qkv = (const float4*)(g_qk + b * Dn);
        float4 qf[6];
        #pragma unroll
        for (int i = 0; i < 6; i++) qf[i] = qkv[i * 32 + lane];

        const float4* xb4 = (const float4*)b_in + ((size_t)b * Sn + (size_t)c * CHUNK_ROWS) * D4;

        // prologue: fill stage 0 (48 KB, 12 float4/thread)
        {
            #pragma unroll
            for (int i = 0; i < 12; i++) {
                int idx = i * 256 + tid;
                cp_async16(sb + idx * 16, xb4 + idx);
            }
            cp_commit();
        }

        float m = -CUDART_INF_F, l = 0.f;
        float4 acc[6];
        #pragma unroll
        for (int i = 0; i < 6; i++) acc[i] = make_float4(0.f, 0.f, 0.f, 0.f);

        for (int t = 0; t < NSTAGE_ITERS; t++) {
            if (t + 1 < NSTAGE_ITERS) {
                const float4* src = xb4 + (size_t)(t + 1) * STAGE_F4;
                unsigned int dst = sb + ((t + 1) & 1) * STAGE_BYTES;
                #pragma unroll
                for (int i = 0; i < 12; i++) {
                    int idx = i * 256 + tid;
                    cp_async16(dst + idx * 16, src + idx);
                }
            }
            cp_commit();
            asm volatile("cp.async.wait_group 1;");
            __syncthreads();

            const float4* stage = smem4 + (size_t)(t & 1) * STAGE_F4;
            const float4* row1 = stage + warp * D4;          // row warp
            const float4* row2 = stage + (warp + 8) * D4;    // row warp+8

            // row1: keep values in registers
            float4 cur1[6];
            #pragma unroll
            for (int i = 0; i < 6; i++) cur1[i] = row1[i * 32 + lane];

            float dot1 = 0.f, dot2 = 0.f;
            #pragma unroll
            for (int i = 0; i < 6; i++) {
                dot1 = fmaf(qf[i].x, cur1[i].x, dot1);
                dot1 = fmaf(qf[i].y, cur1[i].y, dot1);
                dot1 = fmaf(qf[i].z, cur1[i].z, dot1);
                dot1 = fmaf(qf[i].w, cur1[i].w, dot1);
            }
            // row2: streaming dot (values re-read later for the update)
            #pragma unroll
            for (int i = 0; i < 6; i++) {
                float4 x = row2[i * 32 + lane];
                dot2 = fmaf(qf[i].x, x.x, dot2);
                dot2 = fmaf(qf[i].y, x.y, dot2);
                dot2 = fmaf(qf[i].z, x.z, dot2);
                dot2 = fmaf(qf[i].w, x.w, dot2);
            }
            warp_sum2(dot1, dot2);
            float s1 = dot1 * NORM_CONST;
            float s2 = dot2 * NORM_CONST;

            float mn = fmaxf(m, fmaxf(s1, s2));
            float corr = __expf(m - mn);       // first iter: exp(-inf)=0
            float w1 = __expf(s1 - mn);
            float w2 = __expf(s2 - mn);
            l = l * corr + w1 + w2;
            // pass 1: acc = corr*acc + w1*cur1  (cur1 in regs)
            #pragma unroll
            for (int i = 0; i < 6; i++) {
                acc[i].x = fmaf(w1, cur1[i].x, acc[i].x * corr);
                acc[i].y = fmaf(w1, cur1[i].y, acc[i].y * corr);
                acc[i].z = fmaf(w1, cur1[i].z, acc[i].z * corr);
                acc[i].w = fmaf(w1, cur1[i].w, acc[i].w * corr);
            }
            // pass 2: acc += w2*cur2  (re-read row2 from smem)
            #pragma unroll
            for (int i = 0; i < 6; i++) {
                float4 x = row2[i * 32 + lane];
                acc[i].x = fmaf(w2, x.x, acc[i].x);
                acc[i].y = fmaf(w2, x.y, acc[i].y);
                acc[i].z = fmaf(w2, x.z, acc[i].z);
                acc[i].w = fmaf(w2, x.w, acc[i].w);
            }
            m = mn;
            __syncthreads();   // all warps done with stage t before it is refilled
        }

        // merge 8 warp partials -> 1 chunk partial
        #pragma unroll
        for (int i = 0; i < 6; i++) smem4[warp * D4 + i * 32 + lane] = acc[i];
        if (lane == 0) { msm[warp] = m; lsm[warp] = l; }
        __syncthreads();

        if (tid < D4) {
            float M = -CUDART_INF_F;
            #pragma unroll
            for (int w = 0; w < 8; w++) M = fmaxf(M, msm[w]);
            float L = 0.f;
            float4 s = make_float4(0.f, 0.f, 0.f, 0.f);
            #pragma unroll
            for (int w = 0; w < 8; w++) {
                float ef = __expf(msm[w] - M);
                L = fmaf(ef, lsm[w], L);
                float4 a = smem4[w * D4 + tid];
                s.x = fmaf(ef, a.x, s.x);
                s.y = fmaf(ef, a.y, s.y);
                s.z = fmaf(ef, a.z, s.z);
                s.w = fmaf(ef, a.w, s.w);
            }
            ((float4*)g_pacc)[(size_t)blk * D4 + tid] = s;
            if (tid == 0) { g_pm[blk] = M; g_pl[blk] = L; }
        }
    }

    grid_barrier();

    // ---------- Phase B: split-softmax combine (blocks 0..15) ----------
    if (blk < Bn && tid < D4) {
        int b = blk, d4 = tid;
        const float* pm = g_pm + b * CHUNKS_PER_B;
        const float* pl = g_pl + b * CHUNKS_PER_B;
        float M = -CUDART_INF_F;
        #pragma unroll
        for (int j = 0; j < CHUNKS_PER_B; j++) M = fmaxf(M, pm[j]);
        float L = 0.f;
        float4 s = make_float4(0.f, 0.f, 0.f, 0.f);
        const float4* pacc4 = (const float4*)g_pacc;
        #pragma unroll
        for (int j = 0; j < CHUNKS_PER_B; j++) {
            float ef = __expf(pm[j] - M);
            L = fmaf(ef, pl[j], L);
            float4 a = pacc4[(size_t)(b * CHUNKS_PER_B + j) * D4 + d4];
            s.x = fmaf(ef, a.x, s.x);
            s.y = fmaf(ef, a.y, s.y);
            s.z = fmaf(ef, a.z, s.z);
            s.w = fmaf(ef, a.w, s.w);
        }
        float inv = 1.f / L;
        ((float4*)g_c)[b * D4 + d4] = make_float4(s.x * inv, s.y * inv, s.z * inv, s.w * inv);
    }

    grid_barrier();

    // ---------- Phase C: out[b][e] = Wv[e] . c[b], 3 e-rows per block ----------
    {
        const float4* src4 = (const float4*)g_c;
        #pragma unroll
        for (int i = 0; i < 12; i++) {
            int idx = i * 256 + tid;
            cp_async16(sb + idx * 16, src4 + idx);
        }
        cp_commit();

        int e = blk * 3 + warp;
        float4 wf[6];
        if (warp < 3) {
            const float4* wr = (const float4*)(Wv + (size_t)e * Dn);
            #pragma unroll
            for (int i = 0; i < 6; i++) wf[i] = wr[i * 32 + lane];
        }
        cp_wait_all();
        __syncthreads();

        if (warp < 3) {
            const float4* xs4 = (const float4*)smem;
            float acc[Bn];
            #pragma unroll
            for (int b = 0; b < Bn; b++) acc[b] = 0.f;
            #pragma unroll
            for (int i = 0; i < 6; i++) {
                float4 w = wf[i];
                #pragma unroll
                for (int b = 0; b < Bn; b++) {
                    float4 x = xs4[b * D4 + i * 32 + lane];
                    acc[b] = fmaf(w.x, x.x, fmaf(w.y, x.y, fmaf(w.z, x.z, fmaf(w.w, x.w, acc[b]))));
                }
            }
            #pragma unroll
            for (int b = 0; b < Bn; b++) {
                float v = warp_sum(acc[b]);
                if (lane == 0) out[b * Dn + e] = v;
            }
        }
    }
}

// ---------------- launch ----------------
extern "C" void kernel_launch(void* const* d_in, const int* in_sizes, int n_in,
                              void* d_out, int out_size)
{
    const float* b_in = (const float*)d_in[0];
    // d_in[1] = mask (int64): masks whole QUERY rows only; query row 0 is always
    // unmasked and the output only uses query row 0 -> mask is irrelevant.
    const float* Wq = (const float*)d_in[2];
    const float* Wk = (const float*)d_in[3];
    const float* Wv = (const float*)d_in[4];
    float* out = (float*)d_out;

    float* qk; cudaGetSymbolAddress((void**)&qk, g_qk);

    cudaFuncSetAttribute(fused_q0qk, cudaFuncAttributeMaxDynamicSharedMemorySize, 49152);
    cudaFuncSetAttribute(fused_tail, cudaFuncAttributeMaxDynamicSharedMemorySize,
                         ATT_STAGES * STAGE_BYTES);

    cudaMemsetAsync(qk, 0, Bn * Dn * sizeof(float), 0);
    fused_q0qk<<<96, 256, 49152>>>(qk, Wq, Wk, b_in);
    fused_tail<<<NBLK, 256, ATT_STAGES * STAGE_BYTES>>>(b_in, Wv, out);
}